// round 6
// baseline (speedup 1.0000x reference)
#include <cuda_runtime.h>
#include <cuda_bf16.h>

// HorizontalDilation: out[r][c] = max(0, max_{d=-7..7} in[r][c+d]), zero padding.
// Window k=15. Zero padding + final relu => OOB values can be treated as 0.0f.
//
// Round-5 design (resubmit; prior attempt hit an infra failure, never ran):
// one-shot warps (round-3 shape), 16 cols/lane, MLP=4.
//  - Lane l owns cols col0..col0+15, col0 = 480*chunk - 16 + 16*l.
//    Four independent aligned float4 loads -> 4 outstanding LDGs per thread.
//  - +/-7 window spans lanes l-1..l+1 only. Full prefix maxes pre1..15 and
//    suffix maxes suf1..15; neighbors contribute via 14 warp shuffles:
//      out[j] = max(suf_{7-j}[l-1], pre_{j+8}, 0)        j = 0..6
//      out[7] = max(pre15, 0);  out[8] = max(suf15, 0)
//      out[j] = max(suf_{23-j}, pre_{j-8}[l+1], 0)       j = 9..15
//  - Lanes 1..30 store 480 cols exactly tiling [480c, 480c+480); lanes 0/31
//    are halo loaders. 16 | 4096 -> each group fully in or out (one predicate).
//  - 9 chunks cover a row; grid = (3 blocks x 3 warps, 4096 rows).

#define IMG_W 4096
#define IMG_H 4096
#define OUT_PER_WARP 480
#define WARPS_PER_BLOCK 3
#define THREADS (WARPS_PER_BLOCK * 32)   // 96

__global__ __launch_bounds__(THREADS)
void HorizontalDilation_kernel(const float* __restrict__ in, float* __restrict__ out) {
    const unsigned FULL = 0xffffffffu;
    const int lane  = threadIdx.x & 31;
    const int warp  = threadIdx.x >> 5;
    const int chunk = blockIdx.x * WARPS_PER_BLOCK + warp;     // 0..8
    const int row   = blockIdx.y;
    const int col0  = chunk * OUT_PER_WARP - 16 + 16 * lane;   // lane's 16-col group

    // 16 | IMG_W -> group is fully in-bounds or fully out (single predicate).
    const bool inb = (col0 >= 0) & (col0 + 16 <= IMG_W);

    const float* __restrict__ p = in + (size_t)row * IMG_W + col0;

    // Four independent loads issued before any compute (MLP = 4).
    float4 A = make_float4(0.f,0.f,0.f,0.f), B = A, C4 = A, D = A;
    if (inb) {
        A  = *(const float4*)(p);
        B  = *(const float4*)(p + 4);
        C4 = *(const float4*)(p + 8);
        D  = *(const float4*)(p + 12);
    }

    // v0..v15 = A.xyzw B.xyzw C4.xyzw D.xyzw
    // Suffix maxes suf_i = max of last i elements; prefix pre_i = first i.
    const float suf1  = D.w;
    const float suf2  = fmaxf(D.z, suf1);
    const float suf3  = fmaxf(D.y, suf2);
    const float suf4  = fmaxf(D.x, suf3);
    const float suf5  = fmaxf(C4.w, suf4);
    const float suf6  = fmaxf(C4.z, suf5);
    const float suf7  = fmaxf(C4.y, suf6);
    const float suf8  = fmaxf(C4.x, suf7);
    const float suf9  = fmaxf(B.w, suf8);
    const float suf10 = fmaxf(B.z, suf9);
    const float suf11 = fmaxf(B.y, suf10);
    const float suf12 = fmaxf(B.x, suf11);
    const float suf13 = fmaxf(A.w, suf12);
    const float suf14 = fmaxf(A.z, suf13);
    const float suf15 = fmaxf(A.y, suf14);

    const float pre1  = A.x;
    const float pre2  = fmaxf(pre1,  A.y);
    const float pre3  = fmaxf(pre2,  A.z);
    const float pre4  = fmaxf(pre3,  A.w);
    const float pre5  = fmaxf(pre4,  B.x);
    const float pre6  = fmaxf(pre5,  B.y);
    const float pre7  = fmaxf(pre6,  B.z);
    const float pre8  = fmaxf(pre7,  B.w);
    const float pre9  = fmaxf(pre8,  C4.x);
    const float pre10 = fmaxf(pre9,  C4.y);
    const float pre11 = fmaxf(pre10, C4.z);
    const float pre12 = fmaxf(pre11, C4.w);
    const float pre13 = fmaxf(pre12, D.x);
    const float pre14 = fmaxf(pre13, D.y);
    const float pre15 = fmaxf(pre14, D.z);

    // Neighbor aggregates (14 shuffles for 16 outputs).
    const float sU1 = __shfl_up_sync(FULL, suf1, 1);
    const float sU2 = __shfl_up_sync(FULL, suf2, 1);
    const float sU3 = __shfl_up_sync(FULL, suf3, 1);
    const float sU4 = __shfl_up_sync(FULL, suf4, 1);
    const float sU5 = __shfl_up_sync(FULL, suf5, 1);
    const float sU6 = __shfl_up_sync(FULL, suf6, 1);
    const float sU7 = __shfl_up_sync(FULL, suf7, 1);
    const float pD1 = __shfl_down_sync(FULL, pre1, 1);
    const float pD2 = __shfl_down_sync(FULL, pre2, 1);
    const float pD3 = __shfl_down_sync(FULL, pre3, 1);
    const float pD4 = __shfl_down_sync(FULL, pre4, 1);
    const float pD5 = __shfl_down_sync(FULL, pre5, 1);
    const float pD6 = __shfl_down_sync(FULL, pre6, 1);
    const float pD7 = __shfl_down_sync(FULL, pre7, 1);

    float4 o0, o1, o2, o3;
    o0.x = fmaxf(fmaxf(sU7, pre8),  0.f);   // j=0
    o0.y = fmaxf(fmaxf(sU6, pre9),  0.f);   // j=1
    o0.z = fmaxf(fmaxf(sU5, pre10), 0.f);   // j=2
    o0.w = fmaxf(fmaxf(sU4, pre11), 0.f);   // j=3
    o1.x = fmaxf(fmaxf(sU3, pre12), 0.f);   // j=4
    o1.y = fmaxf(fmaxf(sU2, pre13), 0.f);   // j=5
    o1.z = fmaxf(fmaxf(sU1, pre14), 0.f);   // j=6
    o1.w = fmaxf(pre15, 0.f);               // j=7
    o2.x = fmaxf(suf15, 0.f);               // j=8
    o2.y = fmaxf(fmaxf(suf14, pD1), 0.f);   // j=9
    o2.z = fmaxf(fmaxf(suf13, pD2), 0.f);   // j=10
    o2.w = fmaxf(fmaxf(suf12, pD3), 0.f);   // j=11
    o3.x = fmaxf(fmaxf(suf11, pD4), 0.f);   // j=12
    o3.y = fmaxf(fmaxf(suf10, pD5), 0.f);   // j=13
    o3.z = fmaxf(fmaxf(suf9,  pD6), 0.f);   // j=14
    o3.w = fmaxf(fmaxf(suf8,  pD7), 0.f);   // j=15

    // Lanes 1..30 store their own 16 columns (exact tiling of the chunk).
    if (inb & (lane >= 1) & (lane <= 30)) {
        float* q = out + (size_t)row * IMG_W + col0;
        __stcs((float4*)(q),      o0);
        __stcs((float4*)(q + 4),  o1);
        __stcs((float4*)(q + 8),  o2);
        __stcs((float4*)(q + 12), o3);
    }
}

extern "C" void kernel_launch(void* const* d_in, const int* in_sizes, int n_in,
                              void* d_out, int out_size) {
    const float* img = (const float*)d_in[0];
    float* outp = (float*)d_out;
    (void)in_sizes; (void)n_in; (void)out_size;

    // 9 chunks/row = 3 blocks x 3 warps; one grid row per image row.
    dim3 grid(3, IMG_H);
    dim3 block(THREADS);
    HorizontalDilation_kernel<<<grid, block>>>(img, outp);
}

// round 7
// speedup vs baseline: 1.1692x; 1.1692x over previous
#include <cuda_runtime.h>
#include <cuda_bf16.h>

// HorizontalDilation: out[r][c] = max(0, max_{d=-7..7} in[r][c+d]), zero padding.
// Window k=15. Zero padding + final relu => OOB values can be treated as 0.0f.
//
// Round-7 design: perfectly-coalesced 4-cols/lane (round-2 scheme) x 4 rows
// per warp => MLP=4 with ZERO L1 wavefront amplification.
//  - Lane l owns cols col0..col0+3, col0 = 112*chunk - 8 + 4*l: adjacent
//    lanes 16B apart -> every LDG.128/STG.128 is 512B warp-contiguous.
//  - Each warp processes 4 consecutive rows of its chunk; all 4 row-loads are
//    issued before any compute (4 outstanding LDGs per thread).
//  - +/-7 window spans groups l-2..l+2; per row: group prefix/suffix maxes +
//    8 warp shuffles. Lanes 2..29 store 112 cols; lanes 0,1,30,31 are halo.
//  - Grid (37 chunks, 256 row-quads) x 4 warps: warp w of a block handles
//    rows blockIdx.y*16 + 4*w .. +3. No div/mod, no idle warps.

#define IMG_W 4096
#define IMG_H 4096
#define OUT_PER_WARP 112
#define WARPS_PER_BLOCK 4
#define THREADS (WARPS_PER_BLOCK * 32)   // 128
#define ROWS_PER_WARP 4

__global__ __launch_bounds__(THREADS)
void HorizontalDilation_kernel(const float* __restrict__ in, float* __restrict__ out) {
    const unsigned FULL = 0xffffffffu;
    const int lane  = threadIdx.x & 31;
    const int warp  = threadIdx.x >> 5;
    const int col0  = blockIdx.x * OUT_PER_WARP - 8 + 4 * lane;  // lane's 4-col group
    const int row0  = blockIdx.y * (WARPS_PER_BLOCK * ROWS_PER_WARP) + warp * ROWS_PER_WARP;

    // 4 | IMG_W -> group fully in-bounds or fully out (single predicate).
    const bool inb = (col0 >= 0) & (col0 < IMG_W);
    const bool wr  = inb & (lane >= 2) & (lane <= 29);

    const float* __restrict__ p = in  + (size_t)row0 * IMG_W + col0;
    float*       __restrict__ q = out + (size_t)row0 * IMG_W + col0;

    // Issue all 4 row-loads before any compute (MLP = 4, each 512B coalesced).
    float4 v[ROWS_PER_WARP];
    #pragma unroll
    for (int i = 0; i < ROWS_PER_WARP; i++) {
        v[i] = inb ? *(const float4*)(p + (size_t)i * IMG_W)
                   : make_float4(0.f, 0.f, 0.f, 0.f);
    }

    #pragma unroll
    for (int i = 0; i < ROWS_PER_WARP; i++) {
        const float4 a = v[i];

        // Group aggregates: suffix maxes, prefix maxes, full max.
        const float suf1 = a.w;
        const float suf2 = fmaxf(a.z, suf1);
        const float suf3 = fmaxf(a.y, suf2);
        const float m4   = fmaxf(a.x, suf3);
        const float pre1 = a.x;
        const float pre2 = fmaxf(pre1, a.y);
        const float pre3 = fmaxf(pre2, a.z);

        // Neighbor aggregates via shuffles (valid for producer lanes 2..29).
        const float m4_m1 = __shfl_up_sync  (FULL, m4,   1);  // group l-1
        const float m4_p1 = __shfl_down_sync(FULL, m4,   1);  // group l+1
        const float s1    = __shfl_up_sync  (FULL, suf1, 2);  // group l-2
        const float s2    = __shfl_up_sync  (FULL, suf2, 2);
        const float s3    = __shfl_up_sync  (FULL, suf3, 2);
        const float p1    = __shfl_down_sync(FULL, pre1, 2);  // group l+2
        const float p2    = __shfl_down_sync(FULL, pre2, 2);
        const float p3    = __shfl_down_sync(FULL, pre3, 2);

        // Windows for outputs at cols col0+j:
        //  j=0: suf3[l-2] | m4[l-1..l+1]
        //  j=1: suf2[l-2] | core | pre1[l+2]
        //  j=2: suf1[l-2] | core | pre2[l+2]
        //  j=3:            core | pre3[l+2]
        const float core = fmaxf(fmaxf(m4_m1, m4), fmaxf(m4_p1, 0.f));
        float4 o;
        o.x = fmaxf(core, s3);
        o.y = fmaxf(fmaxf(core, s2), p1);
        o.z = fmaxf(fmaxf(core, s1), p2);
        o.w = fmaxf(core, p3);

        if (wr) {
            __stcs((float4*)(q + (size_t)i * IMG_W), o);
        }
    }
}

extern "C" void kernel_launch(void* const* d_in, const int* in_sizes, int n_in,
                              void* d_out, int out_size) {
    const float* img = (const float*)d_in[0];
    float* outp = (float*)d_out;
    (void)in_sizes; (void)n_in; (void)out_size;

    // 37 chunks of 112 cols cover 4096; 256 blocks of 16 rows cover 4096 rows.
    dim3 grid(37, IMG_H / (WARPS_PER_BLOCK * ROWS_PER_WARP));   // (37, 256)
    dim3 block(THREADS);
    HorizontalDilation_kernel<<<grid, block>>>(img, outp);
}

// round 10
// speedup vs baseline: 1.2702x; 1.0864x over previous
#include <cuda_runtime.h>
#include <cuda_bf16.h>

// HorizontalDilation: out[r][c] = max(0, max_{d=-7..7} in[r][c+d]), zero padding.
// Window k=15. Zero padding + final relu => OOB values can be treated as 0.0f.
//
// Round-8 design (2nd resubmit; prior two attempts hit infra failures, never ran):
// 4 cols/lane (perfect 512B coalescing) x 8 rows per warp.
//  - Lane l owns cols col0..col0+3, col0 = 112*blockIdx.x - 8 + 4*l: adjacent
//    lanes 16B apart -> every LDG.128/STG.128 is 512B warp-contiguous.
//  - Each warp processes 8 consecutive rows; ALL 8 row-loads are issued
//    before any compute => MLP=8, 4KB in flight per warp.
//  - +/-7 window spans groups l-2..l+2; per row: prefix/suffix maxes + 8
//    warp shuffles. Lanes 2..29 store 112 cols; lanes 0,1,30,31 are halo.
//  - Grid (37, 128) x 4 warps = 4736 blocks (half the churn of round 7).

#define IMG_W 4096
#define IMG_H 4096
#define OUT_PER_WARP 112
#define WARPS_PER_BLOCK 4
#define THREADS (WARPS_PER_BLOCK * 32)   // 128
#define ROWS_PER_WARP 8

__global__ __launch_bounds__(THREADS)
void HorizontalDilation_kernel(const float* __restrict__ in, float* __restrict__ out) {
    const unsigned FULL = 0xffffffffu;
    const int lane  = threadIdx.x & 31;
    const int warp  = threadIdx.x >> 5;
    const int col0  = blockIdx.x * OUT_PER_WARP - 8 + 4 * lane;  // lane's 4-col group
    const int row0  = (blockIdx.y * WARPS_PER_BLOCK + warp) * ROWS_PER_WARP;

    // 4 | IMG_W -> group fully in-bounds or fully out (single predicate).
    const bool inb = (col0 >= 0) & (col0 < IMG_W);
    const bool wr  = inb & (lane >= 2) & (lane <= 29);

    const float* __restrict__ p = in  + (size_t)row0 * IMG_W + col0;
    float*       __restrict__ q = out + (size_t)row0 * IMG_W + col0;

    // Issue all 8 row-loads before any compute (MLP = 8, each 512B coalesced).
    float4 v[ROWS_PER_WARP];
    #pragma unroll
    for (int i = 0; i < ROWS_PER_WARP; i++) {
        v[i] = inb ? *(const float4*)(p + (size_t)i * IMG_W)
                   : make_float4(0.f, 0.f, 0.f, 0.f);
    }

    #pragma unroll
    for (int i = 0; i < ROWS_PER_WARP; i++) {
        const float4 a = v[i];

        // Group aggregates: suffix maxes, prefix maxes, full max.
        const float suf1 = a.w;
        const float suf2 = fmaxf(a.z, suf1);
        const float suf3 = fmaxf(a.y, suf2);
        const float m4   = fmaxf(a.x, suf3);
        const float pre1 = a.x;
        const float pre2 = fmaxf(pre1, a.y);
        const float pre3 = fmaxf(pre2, a.z);

        // Neighbor aggregates via shuffles (valid for producer lanes 2..29).
        const float m4_m1 = __shfl_up_sync  (FULL, m4,   1);  // group l-1
        const float m4_p1 = __shfl_down_sync(FULL, m4,   1);  // group l+1
        const float s1    = __shfl_up_sync  (FULL, suf1, 2);  // group l-2
        const float s2    = __shfl_up_sync  (FULL, suf2, 2);
        const float s3    = __shfl_up_sync  (FULL, suf3, 2);
        const float p1    = __shfl_down_sync(FULL, pre1, 2);  // group l+2
        const float p2    = __shfl_down_sync(FULL, pre2, 2);
        const float p3    = __shfl_down_sync(FULL, pre3, 2);

        // Windows for outputs at cols col0+j:
        //  j=0: suf3[l-2] | m4[l-1..l+1]
        //  j=1: suf2[l-2] | core | pre1[l+2]
        //  j=2: suf1[l-2] | core | pre2[l+2]
        //  j=3:            core | pre3[l+2]
        const float core = fmaxf(fmaxf(m4_m1, m4), fmaxf(m4_p1, 0.f));
        float4 o;
        o.x = fmaxf(core, s3);
        o.y = fmaxf(fmaxf(core, s2), p1);
        o.z = fmaxf(fmaxf(core, s1), p2);
        o.w = fmaxf(core, p3);

        if (wr) {
            __stcs((float4*)(q + (size_t)i * IMG_W), o);
        }
    }
}

extern "C" void kernel_launch(void* const* d_in, const int* in_sizes, int n_in,
                              void* d_out, int out_size) {
    const float* img = (const float*)d_in[0];
    float* outp = (float*)d_out;
    (void)in_sizes; (void)n_in; (void)out_size;

    // 37 chunks of 112 cols cover 4096; 128 blocks x (4 warps x 8 rows) = 4096 rows.
    dim3 grid(37, IMG_H / (WARPS_PER_BLOCK * ROWS_PER_WARP));   // (37, 128)
    dim3 block(THREADS);
    HorizontalDilation_kernel<<<grid, block>>>(img, outp);
}

// round 12
// speedup vs baseline: 1.2936x; 1.0184x over previous
#include <cuda_runtime.h>
#include <cuda_bf16.h>
#include <cstdint>

// HorizontalDilation: out[r][c] = max(0, max_{d=-7..7} in[r][c+d]), zero padding.
// Window k=15. Zero padding + final relu => OOB values can be treated as 0.0f.
//
// Round-11 (resubmit; prior attempt hit an infra failure, never ran):
// round-10 geometry, but loads forced into SASS-level MLP=8.
//  - 4 cols/lane, 16B lane stride -> every LDG.128/STG.128 is 512B
//    warp-contiguous (zero L1 wavefront amplification).
//  - 8 rows per warp; the 8 row-loads are asm-volatile predicated
//    ld.global.nc.v4 issued back-to-back: ptxas cannot sink them (round 10
//    showed it does exactly that at default reg budget, killing MLP).
//  - __launch_bounds__(128, 6): reg cap 85, room for 32 data regs + temps.
//  - +/-7 window spans groups l-2..l+2; 8 shuffles/row; lanes 2..29 store.

#define IMG_W 4096
#define IMG_H 4096
#define OUT_PER_WARP 112
#define WARPS_PER_BLOCK 4
#define THREADS (WARPS_PER_BLOCK * 32)   // 128
#define ROWS_PER_WARP 8

// Predicated 128-bit load: if pred==0 yields zeros and performs NO memory
// access (safe for OOB addresses). asm volatile pins issue order.
#define LDG4_PRED(vv, ptr, predu)                                          \
    asm volatile("{\n\t"                                                   \
        ".reg .pred p;\n\t"                                                \
        "setp.ne.u32 p, %5, 0;\n\t"                                        \
        "mov.f32 %0, 0f00000000;\n\t"                                      \
        "mov.f32 %1, 0f00000000;\n\t"                                      \
        "mov.f32 %2, 0f00000000;\n\t"                                      \
        "mov.f32 %3, 0f00000000;\n\t"                                      \
        "@p ld.global.nc.v4.f32 {%0, %1, %2, %3}, [%4];\n\t"               \
        "}"                                                                \
        : "=f"((vv).x), "=f"((vv).y), "=f"((vv).z), "=f"((vv).w)           \
        : "l"(ptr), "r"(predu))

__global__ __launch_bounds__(THREADS, 6)
void HorizontalDilation_kernel(const float* __restrict__ in, float* __restrict__ out) {
    const unsigned FULL = 0xffffffffu;
    const int lane  = threadIdx.x & 31;
    const int warp  = threadIdx.x >> 5;
    const int col0  = blockIdx.x * OUT_PER_WARP - 8 + 4 * lane;  // lane's 4-col group
    const int row0  = (blockIdx.y * WARPS_PER_BLOCK + warp) * ROWS_PER_WARP;

    // 4 | IMG_W -> group fully in-bounds or fully out (single predicate).
    const bool inb = (col0 >= 0) & (col0 < IMG_W);
    const unsigned predu = inb ? 1u : 0u;
    const bool wr  = inb & (lane >= 2) & (lane <= 29);

    const float* __restrict__ p = in  + (size_t)row0 * IMG_W + col0;
    float*       __restrict__ q = out + (size_t)row0 * IMG_W + col0;

    // All 8 row-loads issued back-to-back (asm volatile => not sinkable).
    float4 v0, v1, v2, v3, v4, v5, v6, v7;
    LDG4_PRED(v0, p + 0 * (size_t)IMG_W, predu);
    LDG4_PRED(v1, p + 1 * (size_t)IMG_W, predu);
    LDG4_PRED(v2, p + 2 * (size_t)IMG_W, predu);
    LDG4_PRED(v3, p + 3 * (size_t)IMG_W, predu);
    LDG4_PRED(v4, p + 4 * (size_t)IMG_W, predu);
    LDG4_PRED(v5, p + 5 * (size_t)IMG_W, predu);
    LDG4_PRED(v6, p + 6 * (size_t)IMG_W, predu);
    LDG4_PRED(v7, p + 7 * (size_t)IMG_W, predu);

    float4 v[ROWS_PER_WARP] = {v0, v1, v2, v3, v4, v5, v6, v7};

    #pragma unroll
    for (int i = 0; i < ROWS_PER_WARP; i++) {
        const float4 a = v[i];

        // Group aggregates: suffix maxes, prefix maxes, full max.
        const float suf1 = a.w;
        const float suf2 = fmaxf(a.z, suf1);
        const float suf3 = fmaxf(a.y, suf2);
        const float m4   = fmaxf(a.x, suf3);
        const float pre1 = a.x;
        const float pre2 = fmaxf(pre1, a.y);
        const float pre3 = fmaxf(pre2, a.z);

        // Neighbor aggregates via shuffles (valid for producer lanes 2..29).
        const float m4_m1 = __shfl_up_sync  (FULL, m4,   1);  // group l-1
        const float m4_p1 = __shfl_down_sync(FULL, m4,   1);  // group l+1
        const float s1    = __shfl_up_sync  (FULL, suf1, 2);  // group l-2
        const float s2    = __shfl_up_sync  (FULL, suf2, 2);
        const float s3    = __shfl_up_sync  (FULL, suf3, 2);
        const float p1    = __shfl_down_sync(FULL, pre1, 2);  // group l+2
        const float p2    = __shfl_down_sync(FULL, pre2, 2);
        const float p3    = __shfl_down_sync(FULL, pre3, 2);

        // Windows for outputs at cols col0+j:
        //  j=0: suf3[l-2] | m4[l-1..l+1]
        //  j=1: suf2[l-2] | core | pre1[l+2]
        //  j=2: suf1[l-2] | core | pre2[l+2]
        //  j=3:            core | pre3[l+2]
        const float core = fmaxf(fmaxf(m4_m1, m4), fmaxf(m4_p1, 0.f));
        float4 o;
        o.x = fmaxf(core, s3);
        o.y = fmaxf(fmaxf(core, s2), p1);
        o.z = fmaxf(fmaxf(core, s1), p2);
        o.w = fmaxf(core, p3);

        if (wr) {
            __stcs((float4*)(q + (size_t)i * IMG_W), o);
        }
    }
}

extern "C" void kernel_launch(void* const* d_in, const int* in_sizes, int n_in,
                              void* d_out, int out_size) {
    const float* img = (const float*)d_in[0];
    float* outp = (float*)d_out;
    (void)in_sizes; (void)n_in; (void)out_size;

    // 37 chunks of 112 cols cover 4096; 128 blocks x (4 warps x 8 rows) = 4096 rows.
    dim3 grid(37, IMG_H / (WARPS_PER_BLOCK * ROWS_PER_WARP));   // (37, 128)
    dim3 block(THREADS);
    HorizontalDilation_kernel<<<grid, block>>>(img, outp);
}